// round 14
// baseline (speedup 1.0000x reference)
#include <cuda_runtime.h>
#include <cuda_bf16.h>
#include <math_constants.h>

#define SEG_B    16384
#define TPB      256
#define WPB      (TPB / 32)
#define KITER    5                      // float4 iterations per thread
#define REG_CAP  (KITER * 4 * TPB)      // 5120 elements

__device__ int g_seg_start[SEG_B + 1];

// ---------- helpers ----------
__device__ __forceinline__ float wsumf(float v) {
    #pragma unroll
    for (int d = 16; d >= 1; d >>= 1)
        v += __shfl_xor_sync(0xffffffffu, v, d);
    return v;
}

// ---------- pass 0: one warp per boundary, 32-ary cooperative search ----------
__global__ void __launch_bounds__(TPB) k_bounds(const int* __restrict__ ids, int n) {
    const int gw   = (blockIdx.x * TPB + threadIdx.x) >> 5;   // warp id == boundary b
    const int lane = threadIdx.x & 31;
    if (gw >= SEG_B) return;
    const int b = gw;

    // windowed range (ids uniform; +-65536 covers 16 sigma), verified with fallback
    long long mean = (long long)b * (n / SEG_B);
    int lo = (int)max(0LL, mean - 65536);
    int hi = (int)min((long long)n, mean + 65536);
    bool ok = (lo == 0 || __ldg(ids + lo) < b) && (hi == n || __ldg(ids + hi) >= b);
    if (!ok) { lo = 0; hi = n; }

    // invariant: ids[lo-1] < b (or lo==0), ids[hi] >= b (or hi==n)
    while (hi > lo) {
        int W = hi - lo;
        int step = (W + 31) >> 5;                 // >= 1
        int p = lo + lane * step;
        bool pred = (p >= hi) || (__ldg(ids + p) >= b);
        unsigned mask = __ballot_sync(0xffffffffu, pred);
        if (mask == 0u) {                         // all 32 probes < b
            lo = lo + 31 * step + 1;              // ids[lo + 31*step] < b
            continue;
        }
        int first = __ffs(mask) - 1;
        int newhi = lo + first * step;
        if (first == 0) { hi = newhi; break; }    // newhi == lo -> answer lo
        lo = lo + (first - 1) * step + 1;         // ids[prev probe] < b
        hi = min(newhi, hi);
    }

    if (lane == 0) {
        g_seg_start[b] = lo;
        if (b == 0) g_seg_start[SEG_B] = n;
    }
}

// ---------- fused: one block per segment; x read once; minimal predication ----------
__global__ void __launch_bounds__(TPB) k_seg(const float* __restrict__ x,
                                             float* __restrict__ out, int n) {
    __shared__ float sh_red[WPB];
    __shared__ float sh_inv;

    const int s  = blockIdx.x;
    const int st = g_seg_start[s];
    const int en = g_seg_start[s + 1];
    const int len = en - st;
    if (len <= 0) return;

    const int tid = threadIdx.x, lane = tid & 31, wid = tid >> 5;

    if (len <= REG_CAP) {
        const int base4 = st >> 2;
        const int end4  = (en + 3) >> 2;        // 4*end4 <= n always (n % 4 == 0)
        const int nv4   = end4 - base4;
        const int stRem = st & 3;
        const int enRem = en & 3;
        const float4* x4 = reinterpret_cast<const float4*>(x);

        // ---- load (unconditional vector, predicated on idx<nv4 only) ----
        float4 r[KITER];
        #pragma unroll
        for (int k = 0; k < KITER; k++) {
            const int idx = tid + k * TPB;
            r[k] = make_float4(-CUDART_INF_F, -CUDART_INF_F, -CUDART_INF_F, -CUDART_INF_F);
            if (idx < nv4) r[k] = __ldcs(x4 + base4 + idx);
        }

        // ---- patch the two edge float4s with -inf (exp -> 0) ----
        if (tid == 0 && stRem) {
            if (stRem > 0) r[0].x = -CUDART_INF_F;
            if (stRem > 1) r[0].y = -CUDART_INF_F;
            if (stRem > 2) r[0].z = -CUDART_INF_F;
        }
        {
            const int lastIdx = nv4 - 1;
            const int kl = lastIdx >> 8;
            if (enRem && tid == (lastIdx & (TPB - 1))) {
                #pragma unroll
                for (int k = 0; k < KITER; k++) {
                    if (k == kl) {
                        if (enRem <= 1) r[k].y = -CUDART_INF_F;
                        if (enRem <= 2) r[k].z = -CUDART_INF_F;
                        r[k].w = -CUDART_INF_F;
                    }
                }
            }
        }

        // ---- exp in place + local sum ----
        float local = 0.0f;
        #pragma unroll
        for (int k = 0; k < KITER; k++) {
            float e0 = __expf(r[k].x), e1 = __expf(r[k].y);
            float e2 = __expf(r[k].z), e3 = __expf(r[k].w);
            r[k] = make_float4(e0, e1, e2, e3);
            local += (e0 + e1) + (e2 + e3);
        }

        // ---- block reduce ----
        local = wsumf(local);
        if (lane == 0) sh_red[wid] = local;
        __syncthreads();
        if (wid == 0) {
            float v = (lane < WPB) ? sh_red[lane] : 0.0f;
            v = wsumf(v);
            if (lane == 0) sh_inv = 1.0f / v;
        }
        __syncthreads();
        const float inv = sh_inv;

        // ---- store: unconditional STG.128 except the two edge threads ----
        float4* o4 = reinterpret_cast<float4*>(out);
        const int lastIdx = nv4 - 1;
        #pragma unroll
        for (int k = 0; k < KITER; k++) {
            const int idx = tid + k * TPB;
            if (idx < nv4) {
                const bool edgeLo = (idx == 0)       && (stRem != 0);
                const bool edgeHi = (idx == lastIdx) && (enRem != 0);
                if (!(edgeLo || edgeHi)) {
                    float4 ov;
                    ov.x = r[k].x * inv; ov.y = r[k].y * inv;
                    ov.z = r[k].z * inv; ov.w = r[k].w * inv;
                    __stcs(o4 + base4 + idx, ov);
                } else {
                    const int p0 = (base4 + idx) << 2;
                    float vv[4] = {r[k].x, r[k].y, r[k].z, r[k].w};
                    #pragma unroll
                    for (int j = 0; j < 4; j++) {
                        int pos = p0 + j;
                        if (pos >= st && pos < en) out[pos] = vv[j] * inv;
                    }
                }
            }
        }
    } else {
        // ---- fallback: segment larger than register tile (statistically unreachable) ----
        float local = 0.0f;
        for (int pos = st + tid; pos < en; pos += TPB) local += __expf(x[pos]);
        local = wsumf(local);
        if (lane == 0) sh_red[wid] = local;
        __syncthreads();
        if (wid == 0) {
            float v = (lane < WPB) ? sh_red[lane] : 0.0f;
            v = wsumf(v);
            if (lane == 0) sh_inv = 1.0f / v;
        }
        __syncthreads();
        const float inv = sh_inv;
        for (int pos = st + tid; pos < en; pos += TPB)
            out[pos] = __expf(x[pos]) * inv;
    }
}

extern "C" void kernel_launch(void* const* d_in, const int* in_sizes, int n_in,
                              void* d_out, int out_size) {
    const float* x   = (const float*)d_in[0];
    const int*   ids = (const int*)d_in[1];
    float*       out = (float*)d_out;
    int n = in_sizes[0];

    k_bounds<<<(SEG_B * 32 + TPB - 1) / TPB, TPB>>>(ids, n);
    k_seg<<<SEG_B, TPB>>>(x, out, n);
}

// round 17
// speedup vs baseline: 1.2415x; 1.2415x over previous
#include <cuda_runtime.h>
#include <cuda_bf16.h>
#include <math_constants.h>

#define SEG_B    16384
#define TPB      256
#define WPB      (TPB / 32)
#define KITER    5                      // float4 iterations per thread
#define REG_CAP  (KITER * 4 * TPB)      // 5120 elements

__device__ int g_seg_start[SEG_B + 1];

// ---------- helpers ----------
__device__ __forceinline__ float wsumf(float v) {
    #pragma unroll
    for (int d = 16; d >= 1; d >>= 1)
        v += __shfl_xor_sync(0xffffffffu, v, d);
    return v;
}

// ---------- pass 0: per-thread 8-ary search (8 independent probes per round) ----------
__global__ void __launch_bounds__(TPB) k_bounds(const int* __restrict__ ids, int n) {
    int b = blockIdx.x * TPB + threadIdx.x;
    if (b >= SEG_B) return;

    // windowed range (ids uniform; +-65536 covers 16 sigma), verified with fallback
    long long mean = (long long)b * (n / SEG_B);
    int lo = (int)max(0LL, mean - 65536);
    int hi = (int)min((long long)n, mean + 65536);
    bool ok = (lo == 0 || __ldg(ids + lo) < b) && (hi == n || __ldg(ids + hi) >= b);
    if (!ok) { lo = 0; hi = n; }

    // invariant: ids[lo-1] < b (or lo==0), ids[hi] >= b (or hi==n); answer in [lo, hi]
    while (hi > lo) {
        int W = hi - lo;
        int step = (W + 7) >> 3;
        if (step < 1) step = 1;

        int  p[8];
        bool pr[8];
        #pragma unroll
        for (int i = 0; i < 8; i++) {
            int s = lo + i * step;
            p[i] = s;
            int sc = min(s, hi - 1);              // clamp: always in-bounds, independent load
            int v  = __ldg(ids + sc);
            pr[i] = (s >= hi) || (v >= b);
        }

        int first = 8;
        #pragma unroll
        for (int i = 7; i >= 0; i--)
            if (pr[i]) first = i;

        if (first == 8) {
            lo = p[7] + 1;                        // ids[p[7]] < b
        } else {
            hi = min(p[first], hi);               // ids[p[first]] >= b (or past hi)
            if (first > 0) lo = p[first - 1] + 1; // ids[p[first-1]] < b
            // first == 0 -> hi == lo -> loop terminates
        }
    }

    g_seg_start[b] = lo;
    if (b == 0) g_seg_start[SEG_B] = n;
}

// ---------- fused: one block per segment; x read once; minimal predication ----------
__global__ void __launch_bounds__(TPB) k_seg(const float* __restrict__ x,
                                             float* __restrict__ out, int n) {
    __shared__ float sh_red[WPB];
    __shared__ float sh_inv;

    const int s  = blockIdx.x;
    const int st = g_seg_start[s];
    const int en = g_seg_start[s + 1];
    const int len = en - st;
    if (len <= 0) return;

    const int tid = threadIdx.x, lane = tid & 31, wid = tid >> 5;

    if (len <= REG_CAP) {
        const int base4 = st >> 2;
        const int end4  = (en + 3) >> 2;        // 4*end4 <= n always (n % 4 == 0)
        const int nv4   = end4 - base4;
        const int stRem = st & 3;
        const int enRem = en & 3;
        const float4* x4 = reinterpret_cast<const float4*>(x);

        // ---- load (unconditional vector, predicated on idx<nv4 only) ----
        float4 r[KITER];
        #pragma unroll
        for (int k = 0; k < KITER; k++) {
            const int idx = tid + k * TPB;
            r[k] = make_float4(-CUDART_INF_F, -CUDART_INF_F, -CUDART_INF_F, -CUDART_INF_F);
            if (idx < nv4) r[k] = __ldcs(x4 + base4 + idx);
        }

        // ---- patch the two edge float4s with -inf (exp -> 0) ----
        if (tid == 0 && stRem) {
            if (stRem > 0) r[0].x = -CUDART_INF_F;
            if (stRem > 1) r[0].y = -CUDART_INF_F;
            if (stRem > 2) r[0].z = -CUDART_INF_F;
        }
        {
            const int lastIdx = nv4 - 1;
            const int kl = lastIdx >> 8;
            if (enRem && tid == (lastIdx & (TPB - 1))) {
                #pragma unroll
                for (int k = 0; k < KITER; k++) {
                    if (k == kl) {
                        if (enRem <= 1) r[k].y = -CUDART_INF_F;
                        if (enRem <= 2) r[k].z = -CUDART_INF_F;
                        r[k].w = -CUDART_INF_F;
                    }
                }
            }
        }

        // ---- exp in place + local sum ----
        float local = 0.0f;
        #pragma unroll
        for (int k = 0; k < KITER; k++) {
            float e0 = __expf(r[k].x), e1 = __expf(r[k].y);
            float e2 = __expf(r[k].z), e3 = __expf(r[k].w);
            r[k] = make_float4(e0, e1, e2, e3);
            local += (e0 + e1) + (e2 + e3);
        }

        // ---- block reduce ----
        local = wsumf(local);
        if (lane == 0) sh_red[wid] = local;
        __syncthreads();
        if (wid == 0) {
            float v = (lane < WPB) ? sh_red[lane] : 0.0f;
            v = wsumf(v);
            if (lane == 0) sh_inv = 1.0f / v;
        }
        __syncthreads();
        const float inv = sh_inv;

        // ---- store: unconditional STG.128 except the two edge threads ----
        float4* o4 = reinterpret_cast<float4*>(out);
        const int lastIdx = nv4 - 1;
        #pragma unroll
        for (int k = 0; k < KITER; k++) {
            const int idx = tid + k * TPB;
            if (idx < nv4) {
                const bool edgeLo = (idx == 0)       && (stRem != 0);
                const bool edgeHi = (idx == lastIdx) && (enRem != 0);
                if (!(edgeLo || edgeHi)) {
                    float4 ov;
                    ov.x = r[k].x * inv; ov.y = r[k].y * inv;
                    ov.z = r[k].z * inv; ov.w = r[k].w * inv;
                    __stcs(o4 + base4 + idx, ov);
                } else {
                    const int p0 = (base4 + idx) << 2;
                    float vv[4] = {r[k].x, r[k].y, r[k].z, r[k].w};
                    #pragma unroll
                    for (int j = 0; j < 4; j++) {
                        int pos = p0 + j;
                        if (pos >= st && pos < en) out[pos] = vv[j] * inv;
                    }
                }
            }
        }
    } else {
        // ---- fallback: segment larger than register tile (statistically unreachable) ----
        float local = 0.0f;
        for (int pos = st + tid; pos < en; pos += TPB) local += __expf(x[pos]);
        local = wsumf(local);
        if (lane == 0) sh_red[wid] = local;
        __syncthreads();
        if (wid == 0) {
            float v = (lane < WPB) ? sh_red[lane] : 0.0f;
            v = wsumf(v);
            if (lane == 0) sh_inv = 1.0f / v;
        }
        __syncthreads();
        const float inv = sh_inv;
        for (int pos = st + tid; pos < en; pos += TPB)
            out[pos] = __expf(x[pos]) * inv;
    }
}

extern "C" void kernel_launch(void* const* d_in, const int* in_sizes, int n_in,
                              void* d_out, int out_size) {
    const float* x   = (const float*)d_in[0];
    const int*   ids = (const int*)d_in[1];
    float*       out = (float*)d_out;
    int n = in_sizes[0];

    k_bounds<<<(SEG_B + TPB - 1) / TPB, TPB>>>(ids, n);
    k_seg<<<SEG_B, TPB>>>(x, out, n);
}